// round 1
// baseline (speedup 1.0000x reference)
#include <cuda_runtime.h>
#include <cuda_bf16.h>

// ShortConv: RMSNorm(D) -> depthwise causal conv1d (K=4) -> SiLU
// x: (B,L,D) f32, norm_weight: (D,) f32, conv_weight: (K,1,D) f32, out: (B,L,D) f32
// y[b,l,d] = silu( sum_{k=0..3} w[k,d] * nw[d] * x[b,l-3+k,d] * invrms[b,l-3+k] )

#define BDIM 512
#define CHUNK 32

constexpr int Bc = 4;
constexpr int Lc = 4096;
constexpr int Dc = 2048;
constexpr float EPSc = 1e-5f;

__device__ __forceinline__ float silu(float y) {
    return y * __fdividef(1.0f, 1.0f + __expf(-y));
}

__global__ __launch_bounds__(BDIM, 2)
void shortconv_fused_kernel(const float* __restrict__ x,
                            const float* __restrict__ nw,
                            const float* __restrict__ cw,
                            float* __restrict__ out) {
    const int chunks_per_b = Lc / CHUNK;
    const int b  = blockIdx.x / chunks_per_b;
    const int l0 = (blockIdx.x % chunks_per_b) * CHUNK;
    const int tid  = threadIdx.x;
    const int lane = tid & 31;
    const int warp = tid >> 5;
    const int col  = tid * 4;   // 4 contiguous channels per thread (512*4 = 2048 = D)

    __shared__ float sred[32];  // double-buffered 16 warp-partials (parity of l)

    // Load per-channel weights; fold norm_weight into the 4 conv taps.
    float4 nwv = *reinterpret_cast<const float4*>(nw + col);
    float4 w0  = *reinterpret_cast<const float4*>(cw + 0 * Dc + col);
    float4 w1  = *reinterpret_cast<const float4*>(cw + 1 * Dc + col);
    float4 w2  = *reinterpret_cast<const float4*>(cw + 2 * Dc + col);
    float4 w3  = *reinterpret_cast<const float4*>(cw + 3 * Dc + col);
    w0.x *= nwv.x; w0.y *= nwv.y; w0.z *= nwv.z; w0.w *= nwv.w;
    w1.x *= nwv.x; w1.y *= nwv.y; w1.z *= nwv.z; w1.w *= nwv.w;
    w2.x *= nwv.x; w2.y *= nwv.y; w2.z *= nwv.z; w2.w *= nwv.w;
    w3.x *= nwv.x; w3.y *= nwv.y; w3.z *= nwv.z; w3.w *= nwv.w;

    const float* xb = x   + ((size_t)b * Lc) * Dc + col;
    float*       ob = out + ((size_t)b * Lc) * Dc + col;

    const int lstart = (l0 >= 3) ? (l0 - 3) : 0;   // halo warmup rows (no write)
    const int lend   = l0 + CHUNK;

    // Normalized-row history (l-3, l-2, l-1), zero == causal left padding.
    float4 h0 = make_float4(0.f, 0.f, 0.f, 0.f);
    float4 h1 = h0, h2 = h0;

    // Depth-2 register prefetch.
    float4 cur = *reinterpret_cast<const float4*>(xb + (size_t)lstart * Dc);
    float4 nxt = make_float4(0.f, 0.f, 0.f, 0.f);
    if (lstart + 1 < lend)
        nxt = *reinterpret_cast<const float4*>(xb + (size_t)(lstart + 1) * Dc);

    for (int l = lstart; l < lend; ++l) {
        float4 n2 = make_float4(0.f, 0.f, 0.f, 0.f);
        if (l + 2 < lend)
            n2 = *reinterpret_cast<const float4*>(xb + (size_t)(l + 2) * Dc);

        // --- per-row sum of squares, block reduce (1 barrier) ---
        float s = cur.x * cur.x + cur.y * cur.y + cur.z * cur.z + cur.w * cur.w;
        #pragma unroll
        for (int o = 16; o >= 1; o >>= 1)
            s += __shfl_xor_sync(0xffffffffu, s, o);
        if (lane == 0) sred[((l & 1) << 4) + warp] = s;
        __syncthreads();
        float v = (lane < 16) ? sred[((l & 1) << 4) + lane] : 0.0f;
        #pragma unroll
        for (int o = 16; o >= 1; o >>= 1)
            v += __shfl_xor_sync(0xffffffffu, v, o);

        const float inv = rsqrtf(v * (1.0f / Dc) + EPSc);

        float4 xn;
        xn.x = cur.x * inv; xn.y = cur.y * inv; xn.z = cur.z * inv; xn.w = cur.w * inv;

        if (l >= l0) {
            float4 y;
            y.x = w0.x * h0.x + w1.x * h1.x + w2.x * h2.x + w3.x * xn.x;
            y.y = w0.y * h0.y + w1.y * h1.y + w2.y * h2.y + w3.y * xn.y;
            y.z = w0.z * h0.z + w1.z * h1.z + w2.z * h2.z + w3.z * xn.z;
            y.w = w0.w * h0.w + w1.w * h1.w + w2.w * h2.w + w3.w * xn.w;
            y.x = silu(y.x); y.y = silu(y.y); y.z = silu(y.z); y.w = silu(y.w);
            *reinterpret_cast<float4*>(ob + (size_t)l * Dc) = y;
        }

        h0 = h1; h1 = h2; h2 = xn;
        cur = nxt; nxt = n2;
    }
}

extern "C" void kernel_launch(void* const* d_in, const int* in_sizes, int n_in,
                              void* d_out, int out_size) {
    const float* x  = (const float*)d_in[0];
    const float* nw = (const float*)d_in[1];
    const float* cw = (const float*)d_in[2];
    float* out = (float*)d_out;
    (void)in_sizes; (void)n_in; (void)out_size;

    dim3 grid(Bc * (Lc / CHUNK));
    shortconv_fused_kernel<<<grid, BDIM>>>(x, nw, cw, out);
}

// round 2
// speedup vs baseline: 1.0635x; 1.0635x over previous
#include <cuda_runtime.h>
#include <cuda_bf16.h>

// ShortConv: RMSNorm(D) -> depthwise causal conv1d (K=4) -> SiLU
// Two-phase per CTA: (1) streaming sum-of-squares for all rows (no per-row
// barrier), (2) streaming normalize+conv+silu re-reading x from L2.

#define BDIM 512
#define CHUNK 32
#define MAXROWS (CHUNK + 3)

constexpr int Bc = 4;
constexpr int Lc = 4096;
constexpr int Dc = 2048;
constexpr float EPSc = 1e-5f;

__device__ __forceinline__ float silu(float y) {
    return y * __fdividef(1.0f, 1.0f + __expf(-y));
}

__global__ __launch_bounds__(BDIM, 2)
void shortconv_fused_kernel(const float* __restrict__ x,
                            const float* __restrict__ nw,
                            const float* __restrict__ cw,
                            float* __restrict__ out) {
    const int chunks_per_b = Lc / CHUNK;
    const int b  = blockIdx.x / chunks_per_b;
    const int l0 = (blockIdx.x % chunks_per_b) * CHUNK;
    const int tid  = threadIdx.x;
    const int lane = tid & 31;
    const int warp = tid >> 5;
    const int col  = tid * 4;   // 512 threads * 4 ch = 2048 = D

    __shared__ float s_part[MAXROWS * 17];  // per-row, per-warp partials (pad 17)
    __shared__ float s_inv[MAXROWS];        // per-row inv RMS

    const float* xb = x   + ((size_t)b * Lc) * Dc + col;
    float*       ob = out + ((size_t)b * Lc) * Dc + col;

    const int lstart = (l0 >= 3) ? (l0 - 3) : 0;
    const int lend   = l0 + CHUNK;
    const int nrows  = lend - lstart;       // 32 or 35

    // ---------------- Phase 1: per-row sum of squares, no in-loop barrier ----
    #pragma unroll 5
    for (int r = 0; r < nrows; ++r) {
        float4 v = *reinterpret_cast<const float4*>(xb + (size_t)(lstart + r) * Dc);
        float s = v.x * v.x + v.y * v.y + v.z * v.z + v.w * v.w;
        #pragma unroll
        for (int o = 16; o >= 1; o >>= 1)
            s += __shfl_xor_sync(0xffffffffu, s, o);
        if (lane == 0) s_part[r * 17 + warp] = s;
    }
    __syncthreads();

    if (tid < nrows) {
        float s = 0.0f;
        #pragma unroll
        for (int w = 0; w < 16; ++w) s += s_part[tid * 17 + w];
        s_inv[tid] = rsqrtf(s * (1.0f / Dc) + EPSc);
    }
    __syncthreads();

    // ---------------- Phase 2: normalize + conv + silu (no sync at all) -----
    // Fold norm_weight into the conv taps.
    float4 nwv = *reinterpret_cast<const float4*>(nw + col);
    float4 w0  = *reinterpret_cast<const float4*>(cw + 0 * Dc + col);
    float4 w1  = *reinterpret_cast<const float4*>(cw + 1 * Dc + col);
    float4 w2  = *reinterpret_cast<const float4*>(cw + 2 * Dc + col);
    float4 w3  = *reinterpret_cast<const float4*>(cw + 3 * Dc + col);
    w0.x *= nwv.x; w0.y *= nwv.y; w0.z *= nwv.z; w0.w *= nwv.w;
    w1.x *= nwv.x; w1.y *= nwv.y; w1.z *= nwv.z; w1.w *= nwv.w;
    w2.x *= nwv.x; w2.y *= nwv.y; w2.z *= nwv.z; w2.w *= nwv.w;
    w3.x *= nwv.x; w3.y *= nwv.y; w3.z *= nwv.z; w3.w *= nwv.w;

    float4 h0 = make_float4(0.f, 0.f, 0.f, 0.f);
    float4 h1 = h0, h2 = h0;

    float4 cur = *reinterpret_cast<const float4*>(xb + (size_t)lstart * Dc);
    float4 nxt = make_float4(0.f, 0.f, 0.f, 0.f);
    if (lstart + 1 < lend)
        nxt = *reinterpret_cast<const float4*>(xb + (size_t)(lstart + 1) * Dc);

    #pragma unroll 5
    for (int l = lstart; l < lend; ++l) {
        float4 n2 = make_float4(0.f, 0.f, 0.f, 0.f);
        if (l + 2 < lend)
            n2 = *reinterpret_cast<const float4*>(xb + (size_t)(l + 2) * Dc);

        const float inv = s_inv[l - lstart];
        float4 xn;
        xn.x = cur.x * inv; xn.y = cur.y * inv; xn.z = cur.z * inv; xn.w = cur.w * inv;

        if (l >= l0) {
            float4 y;
            y.x = w0.x * h0.x + w1.x * h1.x + w2.x * h2.x + w3.x * xn.x;
            y.y = w0.y * h0.y + w1.y * h1.y + w2.y * h2.y + w3.y * xn.y;
            y.z = w0.z * h0.z + w1.z * h1.z + w2.z * h2.z + w3.z * xn.z;
            y.w = w0.w * h0.w + w1.w * h1.w + w2.w * h2.w + w3.w * xn.w;
            y.x = silu(y.x); y.y = silu(y.y); y.z = silu(y.z); y.w = silu(y.w);
            // evict-first store: don't let the output stream evict x tiles in L2
            __stcs(reinterpret_cast<float4*>(ob + (size_t)l * Dc), y);
        }

        h0 = h1; h1 = h2; h2 = xn;
        cur = nxt; nxt = n2;
    }
}

extern "C" void kernel_launch(void* const* d_in, const int* in_sizes, int n_in,
                              void* d_out, int out_size) {
    const float* x  = (const float*)d_in[0];
    const float* nw = (const float*)d_in[1];
    const float* cw = (const float*)d_in[2];
    float* out = (float*)d_out;
    (void)in_sizes; (void)n_in; (void)out_size;

    dim3 grid(Bc * (Lc / CHUNK));
    shortconv_fused_kernel<<<grid, BDIM>>>(x, nw, cw, out);
}